// round 2
// baseline (speedup 1.0000x reference)
#include <cuda_runtime.h>
#include <cstddef>

#define BATCH 8
#define CH    512
#define TOK   1024
#define HEADS 8
#define HD    64
#define NHEAD (BATCH*HEADS)   // 64
#define GROUPS 32
#define CPG   16              // CH/GROUPS

// Scratch (alloc-free rule: static __device__ globals)
__device__ float g_n[(size_t)BATCH*CH*TOK];          // groupnormed input  (b,c,t)
__device__ float g_qkv[(size_t)BATCH*3*CH*TOK];      // qkv projections    (b,3c,t)
__device__ float g_attn[(size_t)NHEAD*TOK*TOK];      // attention probs    (head,t,s)  256MB
__device__ float g_net[(size_t)BATCH*CH*TOK];        // attention output   (b,c,t)

// ---------------------------------------------------------------------------
// Kernel 1: GroupNorm.  One block per (b, group).  Group = 16 contiguous
// channels x 1024 tokens = 16384 contiguous floats.
// ---------------------------------------------------------------------------
__global__ void gn_kernel(const float* __restrict__ x,
                          const float* __restrict__ w,
                          const float* __restrict__ bb)
{
    int blk = blockIdx.x;            // b*32 + g
    int b = blk >> 5, g = blk & 31;
    const float* src = x   + ((size_t)b*CH + g*CPG) * TOK;
    float*       dst = g_n + ((size_t)b*CH + g*CPG) * TOK;
    int tid = threadIdx.x;
    const int N = CPG * TOK;         // 16384

    float s = 0.f, ss = 0.f;
    for (int i = tid*4; i < N; i += 256*4) {
        float4 v = *(const float4*)(src + i);
        s  += v.x + v.y + v.z + v.w;
        ss += v.x*v.x + v.y*v.y + v.z*v.z + v.w*v.w;
    }
    // block reduce (8 warps)
    for (int o = 16; o; o >>= 1) {
        s  += __shfl_down_sync(~0u, s,  o);
        ss += __shfl_down_sync(~0u, ss, o);
    }
    __shared__ float shs[8], shq[8];
    __shared__ float f_mu, f_rstd;
    if ((tid & 31) == 0) { shs[tid>>5] = s; shq[tid>>5] = ss; }
    __syncthreads();
    if (tid == 0) {
        float ts = 0.f, tq = 0.f;
        #pragma unroll
        for (int i = 0; i < 8; i++) { ts += shs[i]; tq += shq[i]; }
        float mu  = ts / N;
        float var = tq / N - mu*mu;
        f_mu = mu;
        f_rstd = rsqrtf(var + 1e-5f);
    }
    __syncthreads();
    float mu = f_mu, rstd = f_rstd;

    for (int i = tid*4; i < N; i += 256*4) {
        float4 v = *(const float4*)(src + i);
        int c = g*CPG + (i >> 10);               // same c for all 4 lanes (TOK=1024)
        float sw = w[c] * rstd;
        float sb = bb[c] - mu * sw;
        v.x = v.x*sw + sb; v.y = v.y*sw + sb; v.z = v.z*sw + sb; v.w = v.w*sw + sb;
        *(float4*)(dst + i) = v;
    }
}

// ---------------------------------------------------------------------------
// Kernel 2/6: SGEMM 128x128x8, A row-major [M,K] (weights), B row-major [K,N].
// MODE 0: qkv proj  : B = g_n  (per batch), C = g_qkv, M=1536, no residual
// MODE 1: out proj  : B = g_net(per batch), C = Cout,  M=512,  +bias +residual
// N=1024, K=512 in both modes.
// ---------------------------------------------------------------------------
template<int MODE>
__global__ void sgemm_nn(const float* __restrict__ A,
                         const float* __restrict__ bias,
                         const float* __restrict__ res,
                         float* __restrict__ Cout)
{
    constexpr int N = TOK;
    constexpr int K = CH;
    __shared__ float As[8][128];
    __shared__ float Bs[8][128];

    int z = blockIdx.z;
    const float* Bp;
    float* Cp;
    const float* Rp = nullptr;
    if (MODE == 0) {
        Bp = g_n   + (size_t)z*CH*TOK;
        Cp = g_qkv + (size_t)z*3*CH*TOK;
    } else {
        Bp = g_net + (size_t)z*CH*TOK;
        Cp = Cout  + (size_t)z*CH*TOK;
        Rp = res   + (size_t)z*CH*TOK;
    }

    int m0 = blockIdx.y * 128, n0 = blockIdx.x * 128;
    int tid = threadIdx.x;
    int ar = tid >> 1, ac = (tid & 1) * 4;        // A tile 128x8
    int br = tid >> 5, bc = (tid & 31) * 4;       // B tile 8x128
    int ty = tid >> 4, tx = tid & 15;

    float acc[8][8] = {};

    for (int k0 = 0; k0 < K; k0 += 8) {
        float4 av = *(const float4*)(A  + (size_t)(m0+ar)*K + k0 + ac);
        float4 bv = *(const float4*)(Bp + (size_t)(k0+br)*N + n0 + bc);
        __syncthreads();
        As[ac+0][ar] = av.x; As[ac+1][ar] = av.y;
        As[ac+2][ar] = av.z; As[ac+3][ar] = av.w;
        *(float4*)&Bs[br][bc] = bv;
        __syncthreads();
        #pragma unroll
        for (int k = 0; k < 8; k++) {
            float a[8], b[8];
            #pragma unroll
            for (int i = 0; i < 8; i++) a[i] = As[k][ty*8+i];
            #pragma unroll
            for (int j = 0; j < 8; j++) b[j] = Bs[k][tx*8+j];
            #pragma unroll
            for (int i = 0; i < 8; i++)
                #pragma unroll
                for (int j = 0; j < 8; j++)
                    acc[i][j] += a[i] * b[j];
        }
    }

    #pragma unroll
    for (int i = 0; i < 8; i++) {
        int m = m0 + ty*8 + i;
        float bi = bias[m];
        #pragma unroll
        for (int j = 0; j < 8; j += 4) {
            int n = n0 + tx*8 + j;
            float4 o;
            o.x = acc[i][j+0] + bi; o.y = acc[i][j+1] + bi;
            o.z = acc[i][j+2] + bi; o.w = acc[i][j+3] + bi;
            if (MODE == 1) {
                float4 r = *(const float4*)(Rp + (size_t)m*N + n);
                o.x += r.x; o.y += r.y; o.z += r.z; o.w += r.w;
            }
            *(float4*)(Cp + (size_t)m*N + n) = o;
        }
    }
}

// ---------------------------------------------------------------------------
// Kernel 3: attention scores.  attn[head,t,s] = 0.125 * sum_c q[c,t]*k[c,s]
// qkv per-head layout: head h of batch b owns rows [h*192, h*192+192) of the
// 1536-row qkv buffer: q rows +0..63, k rows +64..127, v rows +128..191.
// Both operands K-major (c-major) -> symmetric coalesced tile loads.
// ---------------------------------------------------------------------------
__global__ void scores_kernel()
{
    int head = blockIdx.z;
    int b = head >> 3, h = head & 7;
    const float* q  = g_qkv + ((size_t)b*3*CH + h*3*HD       ) * TOK;
    const float* kk = g_qkv + ((size_t)b*3*CH + h*3*HD + HD  ) * TOK;
    float* out = g_attn + (size_t)head*TOK*TOK;

    __shared__ float Qs[8][128], Ks[8][128];
    int t0 = blockIdx.y * 128, s0 = blockIdx.x * 128;
    int tid = threadIdx.x;
    int lr = tid >> 5, lc = (tid & 31) * 4;       // 8 x 128 tile loads
    int ty = tid >> 4, tx = tid & 15;

    float acc[8][8] = {};

    for (int k0 = 0; k0 < HD; k0 += 8) {
        float4 qv = *(const float4*)(q  + (size_t)(k0+lr)*TOK + t0 + lc);
        float4 kv = *(const float4*)(kk + (size_t)(k0+lr)*TOK + s0 + lc);
        __syncthreads();
        *(float4*)&Qs[lr][lc] = qv;
        *(float4*)&Ks[lr][lc] = kv;
        __syncthreads();
        #pragma unroll
        for (int k = 0; k < 8; k++) {
            float a[8], bb[8];
            #pragma unroll
            for (int i = 0; i < 8; i++) a[i]  = Qs[k][ty*8+i];
            #pragma unroll
            for (int j = 0; j < 8; j++) bb[j] = Ks[k][tx*8+j];
            #pragma unroll
            for (int i = 0; i < 8; i++)
                #pragma unroll
                for (int j = 0; j < 8; j++)
                    acc[i][j] += a[i] * bb[j];
        }
    }

    #pragma unroll
    for (int i = 0; i < 8; i++) {
        int t = t0 + ty*8 + i;
        #pragma unroll
        for (int j = 0; j < 8; j += 4) {
            int s = s0 + tx*8 + j;
            float4 o;
            o.x = acc[i][j+0]*0.125f; o.y = acc[i][j+1]*0.125f;
            o.z = acc[i][j+2]*0.125f; o.w = acc[i][j+3]*0.125f;
            *(float4*)(out + (size_t)t*TOK + s) = o;
        }
    }
}

// ---------------------------------------------------------------------------
// Kernel 4: row softmax over s.  One block (256 thr) per row, 4 elems/thread.
// ---------------------------------------------------------------------------
__global__ void softmax_kernel()
{
    float* p = g_attn + (size_t)blockIdx.x * TOK;
    int tid = threadIdx.x;
    float4 v = *(const float4*)(p + tid*4);

    float m = fmaxf(fmaxf(v.x, v.y), fmaxf(v.z, v.w));
    for (int o = 16; o; o >>= 1) m = fmaxf(m, __shfl_xor_sync(~0u, m, o));
    __shared__ float sh[8];
    __shared__ float rowmax, rowsum;
    if ((tid & 31) == 0) sh[tid>>5] = m;
    __syncthreads();
    if (tid == 0) {
        float mm = sh[0];
        #pragma unroll
        for (int i = 1; i < 8; i++) mm = fmaxf(mm, sh[i]);
        rowmax = mm;
    }
    __syncthreads();
    m = rowmax;
    v.x = __expf(v.x - m); v.y = __expf(v.y - m);
    v.z = __expf(v.z - m); v.w = __expf(v.w - m);
    float s = v.x + v.y + v.z + v.w;
    for (int o = 16; o; o >>= 1) s += __shfl_xor_sync(~0u, s, o);
    if ((tid & 31) == 0) sh[tid>>5] = s;
    __syncthreads();
    if (tid == 0) {
        float t = 0.f;
        #pragma unroll
        for (int i = 0; i < 8; i++) t += sh[i];
        rowsum = t;
    }
    __syncthreads();
    float inv = 1.f / rowsum;
    v.x *= inv; v.y *= inv; v.z *= inv; v.w *= inv;
    *(float4*)(p + tid*4) = v;
}

// ---------------------------------------------------------------------------
// Kernel 5: net[c,t] = sum_s v[c,s] * prob[t,s].  Per head: M=64, N tile 128,
// BK=16.  prob tile transposed in smem (coalesced loads along s).
// ---------------------------------------------------------------------------
__global__ void pv_kernel()
{
    int head = blockIdx.z;
    int b = head >> 3, h = head & 7;
    const float* vv = g_qkv + ((size_t)b*3*CH + h*3*HD + 2*HD) * TOK;
    const float* pr = g_attn + (size_t)head*TOK*TOK;
    float* out = g_net + ((size_t)b*CH + h*HD) * TOK;

    __shared__ float Vs[16][64];    // [s][c]
    __shared__ float Ps[16][128];   // [s][t]
    int n0 = blockIdx.x * 128;
    int tid = threadIdx.x;
    int vr = tid >> 2, vc = (tid & 3) * 4;   // V tile 64 x 16
    int prow = tid >> 1, pcol = (tid & 1) * 8; // P tile 128 x 16
    int ty = tid >> 4, tx = tid & 15;        // thread: 4 c-rows x 8 t-cols

    float acc[4][8] = {};

    for (int s0 = 0; s0 < TOK; s0 += 16) {
        float4 a  = *(const float4*)(vv + (size_t)vr*TOK + s0 + vc);
        float4 b0 = *(const float4*)(pr + (size_t)(n0+prow)*TOK + s0 + pcol);
        float4 b1 = *(const float4*)(pr + (size_t)(n0+prow)*TOK + s0 + pcol + 4);
        __syncthreads();
        Vs[vc+0][vr] = a.x; Vs[vc+1][vr] = a.y;
        Vs[vc+2][vr] = a.z; Vs[vc+3][vr] = a.w;
        Ps[pcol+0][prow] = b0.x; Ps[pcol+1][prow] = b0.y;
        Ps[pcol+2][prow] = b0.z; Ps[pcol+3][prow] = b0.w;
        Ps[pcol+4][prow] = b1.x; Ps[pcol+5][prow] = b1.y;
        Ps[pcol+6][prow] = b1.z; Ps[pcol+7][prow] = b1.w;
        __syncthreads();
        #pragma unroll
        for (int k = 0; k < 16; k++) {
            float a4[4], bb[8];
            #pragma unroll
            for (int i = 0; i < 4; i++) a4[i] = Vs[k][ty*4+i];
            #pragma unroll
            for (int j = 0; j < 8; j++) bb[j] = Ps[k][tx*8+j];
            #pragma unroll
            for (int i = 0; i < 4; i++)
                #pragma unroll
                for (int j = 0; j < 8; j++)
                    acc[i][j] += a4[i] * bb[j];
        }
    }

    #pragma unroll
    for (int i = 0; i < 4; i++) {
        int c = ty*4 + i;
        #pragma unroll
        for (int j = 0; j < 8; j += 4) {
            int t = n0 + tx*8 + j;
            float4 o;
            o.x = acc[i][j+0]; o.y = acc[i][j+1];
            o.z = acc[i][j+2]; o.w = acc[i][j+3];
            *(float4*)(out + (size_t)c*TOK + t) = o;
        }
    }
}

// ---------------------------------------------------------------------------
extern "C" void kernel_launch(void* const* d_in, const int* in_sizes, int n_in,
                              void* d_out, int out_size)
{
    const float* x     = (const float*)d_in[0];
    const float* gn_w  = (const float*)d_in[1];
    const float* gn_b  = (const float*)d_in[2];
    const float* qkv_w = (const float*)d_in[3];
    const float* qkv_b = (const float*)d_in[4];
    const float* out_w = (const float*)d_in[5];
    const float* out_b = (const float*)d_in[6];
    float* out = (float*)d_out;

    // 1. GroupNorm
    gn_kernel<<<BATCH*GROUPS, 256>>>(x, gn_w, gn_b);

    // 2. QKV projection: (1536x512)x(512x1024) per batch
    sgemm_nn<0><<<dim3(TOK/128, 3*CH/128, BATCH), 256>>>(qkv_w, qkv_b, nullptr, nullptr);

    // 3. Scores: per head 1024x1024, K=64
    scores_kernel<<<dim3(TOK/128, TOK/128, NHEAD), 256>>>();

    // 4. Softmax over rows
    softmax_kernel<<<NHEAD*TOK, 256>>>();

    // 5. net = prob @ v^T
    pv_kernel<<<dim3(TOK/128, 1, NHEAD), 256>>>();

    // 6. Out projection + bias + residual
    sgemm_nn<1><<<dim3(TOK/128, CH/128, BATCH), 256>>>(out_w, out_b, x, out);
}

// round 3
// speedup vs baseline: 6.5760x; 6.5760x over previous
#include <cuda_runtime.h>
#include <cuda_fp16.h>
#include <cstddef>
#include <cstdint>

#define BATCH 8
#define CH    512
#define TOK   1024
#define HEADS 8
#define HD    64
#define NHEAD (BATCH*HEADS)   // 64
#define GROUPS 32
#define CPG   16

// ---------------- scratch (__device__ globals; alloc-free rule) -------------
__device__ __align__(16) __half g_nT  [(size_t)BATCH*TOK*CH];    // [b][t][c]
__device__ __align__(16) __half g_wqkv[(size_t)3*CH*CH];         // [och][c]
__device__ __align__(16) __half g_wout[(size_t)CH*CH];           // [och][c]
__device__ __align__(16) __half g_q   [(size_t)NHEAD*TOK*HD];    // [head][t][c]  (x0.125)
__device__ __align__(16) __half g_k   [(size_t)NHEAD*TOK*HD];    // [head][s][c]
__device__ __align__(16) __half g_v   [(size_t)NHEAD*HD*TOK];    // [head][c][s]
__device__ __align__(16) __half g_netT[(size_t)BATCH*TOK*CH];    // [b][t][c]

// ---------------- mma helper ------------------------------------------------
__device__ __forceinline__ void mma_f16(float* c, const uint32_t* a, const uint32_t* b)
{
    asm volatile(
        "mma.sync.aligned.m16n8k16.row.col.f32.f16.f16.f32 "
        "{%0,%1,%2,%3},{%4,%5,%6,%7},{%8,%9},{%0,%1,%2,%3};"
        : "+f"(c[0]), "+f"(c[1]), "+f"(c[2]), "+f"(c[3])
        : "r"(a[0]), "r"(a[1]), "r"(a[2]), "r"(a[3]), "r"(b[0]), "r"(b[1]));
}

__device__ __forceinline__ uint32_t pack_h2(float lo, float hi)
{
    __half2 h = __floats2half2_rn(lo, hi);
    return *reinterpret_cast<uint32_t*>(&h);
}

// ---------------------------------------------------------------------------
// Kernel 0: convert weights fp32 -> fp16
// ---------------------------------------------------------------------------
__global__ void cvt_w_kernel(const float* __restrict__ qkvw,
                             const float* __restrict__ outw)
{
    int i = blockIdx.x * 256 + threadIdx.x;     // one float4 each
    const int N1 = 3*CH*CH/4;                   // 196608
    const int N2 = CH*CH/4;                     // 65536
    if (i < N1) {
        float4 v = *(const float4*)(qkvw + (size_t)i*4);
        __half* d = g_wqkv + (size_t)i*4;
        d[0]=__float2half_rn(v.x); d[1]=__float2half_rn(v.y);
        d[2]=__float2half_rn(v.z); d[3]=__float2half_rn(v.w);
    } else if (i < N1 + N2) {
        int j = i - N1;
        float4 v = *(const float4*)(outw + (size_t)j*4);
        __half* d = g_wout + (size_t)j*4;
        d[0]=__float2half_rn(v.x); d[1]=__float2half_rn(v.y);
        d[2]=__float2half_rn(v.z); d[3]=__float2half_rn(v.w);
    }
}

// ---------------------------------------------------------------------------
// Kernel 1: GroupNorm -> g_nT[b][t][c] (half), transposed via smem tiles.
// One block per (b, group): group = 16 contiguous channels x 1024 tokens.
// ---------------------------------------------------------------------------
__global__ void gn_kernel(const float* __restrict__ x,
                          const float* __restrict__ w,
                          const float* __restrict__ bb)
{
    int blk = blockIdx.x;
    int b = blk >> 5, gg = blk & 31;
    const float* src = x + ((size_t)b*CH + gg*CPG) * TOK;
    int tid = threadIdx.x;
    const int N = CPG * TOK;   // 16384

    float s = 0.f, ss = 0.f;
    for (int i = tid*4; i < N; i += 256*4) {
        float4 v = *(const float4*)(src + i);
        s  += v.x + v.y + v.z + v.w;
        ss += v.x*v.x + v.y*v.y + v.z*v.z + v.w*v.w;
    }
    for (int o = 16; o; o >>= 1) {
        s  += __shfl_down_sync(~0u, s,  o);
        ss += __shfl_down_sync(~0u, ss, o);
    }
    __shared__ float shs[8], shq[8];
    __shared__ float f_mu, f_rstd;
    if ((tid & 31) == 0) { shs[tid>>5] = s; shq[tid>>5] = ss; }
    __syncthreads();
    if (tid == 0) {
        float ts = 0.f, tq = 0.f;
        #pragma unroll
        for (int i = 0; i < 8; i++) { ts += shs[i]; tq += shq[i]; }
        float mu  = ts / N;
        f_mu = mu;
        f_rstd = rsqrtf(tq / N - mu*mu + 1e-5f);
    }
    __syncthreads();
    float mu = f_mu, rstd = f_rstd;

    // normalize + transpose 16c x 64t tiles
    __shared__ __align__(16) __half tile[16][68];
    int c  = tid >> 4;            // 0..15 (tid*4/64)
    int tl = (tid & 15) * 4;      // 0..60
    float scw = w[gg*CPG + c] * rstd;
    float scb = bb[gg*CPG + c] - mu * scw;
    int tw  = tid >> 2;           // write: t row 0..63
    int c4  = (tid & 3) * 4;      // write: c group
    for (int t0 = 0; t0 < TOK; t0 += 64) {
        float4 v = *(const float4*)(src + (size_t)c*TOK + t0 + tl);
        __half2 h0 = __floats2half2_rn(v.x*scw+scb, v.y*scw+scb);
        __half2 h1 = __floats2half2_rn(v.z*scw+scb, v.w*scw+scb);
        *(__half2*)&tile[c][tl]   = h0;
        *(__half2*)&tile[c][tl+2] = h1;
        __syncthreads();
        __half* dst = g_nT + ((size_t)b*TOK + t0 + tw)*CH + gg*CPG + c4;
        *(__half2*)(dst)   = __halves2half2(tile[c4  ][tw], tile[c4+1][tw]);
        *(__half2*)(dst+2) = __halves2half2(tile[c4+2][tw], tile[c4+3][tw]);
        __syncthreads();
    }
}

// ---------------------------------------------------------------------------
// Kernel 2/4: half GEMM, C[m][n] = sum_k A[m][k] * B[n][k]  (A*B^T), K=512.
// Block tile 128x128, 8 warps (4 m x 2 n), warp tile 32x64.
// MODE 0 (qkv): A = g_nT[b]   (M=1024 t),  B = g_wqkv (N=1536 och)
//               epilogue routes q/k/v (+bias, q scaled 0.125)
// MODE 1 (out): A = g_wout    (M=512 och), B = g_netT[b] (N=1024 t)
//               epilogue: + out_b + residual x, fp32 store to d_out
// ---------------------------------------------------------------------------
template<int MODE>
__global__ void __launch_bounds__(256)
gemm_h(const __half* __restrict__ Abase, const __half* __restrict__ Bbase,
       const float* __restrict__ bias, const float* __restrict__ res,
       float* __restrict__ Cout)
{
    __shared__ __align__(16) __half As[128][40];
    __shared__ __align__(16) __half Bs[128][40];

    int bz = blockIdx.z;
    const __half* A = Abase + (MODE == 0 ? (size_t)bz*TOK*CH : 0);
    const __half* B = Bbase + (MODE == 1 ? (size_t)bz*TOK*CH : 0);

    int m0 = blockIdx.y * 128, n0 = blockIdx.x * 128;
    int tid = threadIdx.x, wid = tid >> 5, lane = tid & 31;
    int g = lane >> 2, tg = lane & 3;
    int wm = wid & 3, wn = wid >> 2;

    int lr = tid >> 2;            // load row 0..63
    int lc = (tid & 3) * 8;       // load col group (8 halves)

    float acc[2][8][4] = {};

    for (int k0 = 0; k0 < CH; k0 += 32) {
        uint4 a0 = *(const uint4*)(A + (size_t)(m0+lr   )*CH + k0 + lc);
        uint4 a1 = *(const uint4*)(A + (size_t)(m0+lr+64)*CH + k0 + lc);
        uint4 b0 = *(const uint4*)(B + (size_t)(n0+lr   )*CH + k0 + lc);
        uint4 b1 = *(const uint4*)(B + (size_t)(n0+lr+64)*CH + k0 + lc);
        __syncthreads();
        *(uint4*)&As[lr   ][lc] = a0;
        *(uint4*)&As[lr+64][lc] = a1;
        *(uint4*)&Bs[lr   ][lc] = b0;
        *(uint4*)&Bs[lr+64][lc] = b1;
        __syncthreads();
        #pragma unroll
        for (int kk = 0; kk < 2; kk++) {
            uint32_t af[2][4], bf[8][2];
            int kc = kk*16 + tg*2;
            #pragma unroll
            for (int i = 0; i < 2; i++) {
                int mr = wm*32 + i*16 + g;
                af[i][0] = *(const uint32_t*)&As[mr  ][kc];
                af[i][1] = *(const uint32_t*)&As[mr+8][kc];
                af[i][2] = *(const uint32_t*)&As[mr  ][kc+8];
                af[i][3] = *(const uint32_t*)&As[mr+8][kc+8];
            }
            #pragma unroll
            for (int j = 0; j < 8; j++) {
                int nr = wn*64 + j*8 + g;
                bf[j][0] = *(const uint32_t*)&Bs[nr][kc];
                bf[j][1] = *(const uint32_t*)&Bs[nr][kc+8];
            }
            #pragma unroll
            for (int i = 0; i < 2; i++)
                #pragma unroll
                for (int j = 0; j < 8; j++)
                    mma_f16(acc[i][j], af[i], bf[j]);
        }
    }

    if (MODE == 0) {
        // C[m=t][n=och]; route to q/k/v
        #pragma unroll
        for (int j = 0; j < 8; j++) {
            int n = n0 + wn*64 + j*8 + tg*2;      // och (pair n, n+1)
            float bi0 = bias[n], bi1 = bias[n+1];
            int hh = n / 192, r = n % 192;
            #pragma unroll
            for (int i = 0; i < 2; i++) {
                int t = m0 + wm*32 + i*16 + g;
                float v00 = acc[i][j][0]+bi0, v01 = acc[i][j][1]+bi1;
                float v10 = acc[i][j][2]+bi0, v11 = acc[i][j][3]+bi1;
                size_t hb = (size_t)(bz*HEADS + hh);
                if (r < 64) {
                    v00*=0.125f; v01*=0.125f; v10*=0.125f; v11*=0.125f;
                    __half* q = g_q + (hb*TOK)*HD + r;
                    *(__half2*)(q + (size_t)t    *HD) = __floats2half2_rn(v00, v01);
                    *(__half2*)(q + (size_t)(t+8)*HD) = __floats2half2_rn(v10, v11);
                } else if (r < 128) {
                    __half* k = g_k + (hb*TOK)*HD + (r-64);
                    *(__half2*)(k + (size_t)t    *HD) = __floats2half2_rn(v00, v01);
                    *(__half2*)(k + (size_t)(t+8)*HD) = __floats2half2_rn(v10, v11);
                } else {
                    int cc = r - 128;
                    __half* v = g_v + (hb*HD + cc)*TOK;
                    v[t]         = __float2half_rn(v00);
                    v[TOK + t]   = __float2half_rn(v01);
                    v[t+8]       = __float2half_rn(v10);
                    v[TOK + t+8] = __float2half_rn(v11);
                }
            }
        }
    } else {
        // C[m=och][n=t]; + bias + residual -> fp32 out
        #pragma unroll
        for (int j = 0; j < 8; j++) {
            int n = n0 + wn*64 + j*8 + tg*2;
            #pragma unroll
            for (int i = 0; i < 2; i++) {
                int m = m0 + wm*32 + i*16 + g;
                float ob0 = bias[m], ob1 = bias[m+8];
                size_t o0 = ((size_t)bz*CH + m)*TOK + n;
                size_t o1 = ((size_t)bz*CH + m+8)*TOK + n;
                float2 r0 = *(const float2*)(res + o0);
                float2 r1 = *(const float2*)(res + o1);
                float2 w0 = { acc[i][j][0]+ob0+r0.x, acc[i][j][1]+ob0+r0.y };
                float2 w1 = { acc[i][j][2]+ob1+r1.x, acc[i][j][3]+ob1+r1.y };
                *(float2*)(Cout + o0) = w0;
                *(float2*)(Cout + o1) = w1;
            }
        }
    }
}

// ---------------------------------------------------------------------------
// Kernel 3: flash attention. One block = (head, 64 q-rows). 128 threads,
// 4 warps, each warp owns 16 q-rows x full 64-s tile.
// ---------------------------------------------------------------------------
__global__ void __launch_bounds__(128) flash_kernel()
{
    int head = blockIdx.y;
    int b = head >> 3, h = head & 7;
    int t0 = blockIdx.x * 64;
    const __half* Qg = g_q + ((size_t)head*TOK + t0)*HD;
    const __half* Kg = g_k + (size_t)head*TOK*HD;
    const __half* Vg = g_v + (size_t)head*HD*TOK;

    __shared__ __align__(16) __half Qs[64][72];
    __shared__ __align__(16) __half Ks[64][72];
    __shared__ __align__(16) __half Vs[64][72];

    int tid = threadIdx.x, wid = tid >> 5, lane = tid & 31;
    int g = lane >> 2, tg = lane & 3;

    #pragma unroll
    for (int p = 0; p < 4; p++) {
        int u = tid + p*128;
        int r = u >> 3, cg = (u & 7) * 8;
        *(uint4*)&Qs[r][cg] = *(const uint4*)(Qg + (size_t)r*HD + cg);
    }
    __syncthreads();

    uint32_t aq[4][4];
    #pragma unroll
    for (int kk = 0; kk < 4; kk++) {
        int mr = wid*16 + g, kc = kk*16 + tg*2;
        aq[kk][0] = *(const uint32_t*)&Qs[mr  ][kc];
        aq[kk][1] = *(const uint32_t*)&Qs[mr+8][kc];
        aq[kk][2] = *(const uint32_t*)&Qs[mr  ][kc+8];
        aq[kk][3] = *(const uint32_t*)&Qs[mr+8][kc+8];
    }

    float m0 = -1e30f, m1 = -1e30f, l0 = 0.f, l1 = 0.f;
    float o[8][4] = {};

    for (int s0 = 0; s0 < TOK; s0 += 64) {
        __syncthreads();
        #pragma unroll
        for (int p = 0; p < 4; p++) {
            int u = tid + p*128;
            int r = u >> 3, cg = (u & 7) * 8;
            *(uint4*)&Ks[r][cg] = *(const uint4*)(Kg + (size_t)(s0+r)*HD + cg);
            *(uint4*)&Vs[r][cg] = *(const uint4*)(Vg + (size_t)r*TOK + s0 + cg);
        }
        __syncthreads();

        float sc[8][4] = {};
        #pragma unroll
        for (int kk = 0; kk < 4; kk++) {
            int kc = kk*16 + tg*2;
            #pragma unroll
            for (int j = 0; j < 8; j++) {
                uint32_t bf[2];
                bf[0] = *(const uint32_t*)&Ks[j*8+g][kc];
                bf[1] = *(const uint32_t*)&Ks[j*8+g][kc+8];
                mma_f16(sc[j], aq[kk], bf);
            }
        }

        // online softmax (rows g and g+8 of this warp's 16-row block)
        float mx0 = -1e30f, mx1 = -1e30f;
        #pragma unroll
        for (int j = 0; j < 8; j++) {
            mx0 = fmaxf(mx0, fmaxf(sc[j][0], sc[j][1]));
            mx1 = fmaxf(mx1, fmaxf(sc[j][2], sc[j][3]));
        }
        mx0 = fmaxf(mx0, __shfl_xor_sync(~0u, mx0, 1));
        mx0 = fmaxf(mx0, __shfl_xor_sync(~0u, mx0, 2));
        mx1 = fmaxf(mx1, __shfl_xor_sync(~0u, mx1, 1));
        mx1 = fmaxf(mx1, __shfl_xor_sync(~0u, mx1, 2));
        float nm0 = fmaxf(m0, mx0), nm1 = fmaxf(m1, mx1);
        float f0 = __expf(m0 - nm0), f1 = __expf(m1 - nm1);
        m0 = nm0; m1 = nm1;
        float s0s = 0.f, s1s = 0.f;
        #pragma unroll
        for (int j = 0; j < 8; j++) {
            sc[j][0] = __expf(sc[j][0] - nm0);
            sc[j][1] = __expf(sc[j][1] - nm0);
            sc[j][2] = __expf(sc[j][2] - nm1);
            sc[j][3] = __expf(sc[j][3] - nm1);
            s0s += sc[j][0] + sc[j][1];
            s1s += sc[j][2] + sc[j][3];
        }
        s0s += __shfl_xor_sync(~0u, s0s, 1);
        s0s += __shfl_xor_sync(~0u, s0s, 2);
        s1s += __shfl_xor_sync(~0u, s1s, 1);
        s1s += __shfl_xor_sync(~0u, s1s, 2);
        l0 = l0*f0 + s0s;
        l1 = l1*f1 + s1s;
        #pragma unroll
        for (int j = 0; j < 8; j++) {
            o[j][0] *= f0; o[j][1] *= f0; o[j][2] *= f1; o[j][3] *= f1;
        }

        // PV: acc[t][c] += P[t][s] * V[s][c]
        #pragma unroll
        for (int i = 0; i < 4; i++) {
            uint32_t ap[4];
            ap[0] = pack_h2(sc[2*i  ][0], sc[2*i  ][1]);
            ap[1] = pack_h2(sc[2*i  ][2], sc[2*i  ][3]);
            ap[2] = pack_h2(sc[2*i+1][0], sc[2*i+1][1]);
            ap[3] = pack_h2(sc[2*i+1][2], sc[2*i+1][3]);
            int kc = i*16 + tg*2;
            #pragma unroll
            for (int jc = 0; jc < 8; jc++) {
                uint32_t bf[2];
                bf[0] = *(const uint32_t*)&Vs[jc*8+g][kc];
                bf[1] = *(const uint32_t*)&Vs[jc*8+g][kc+8];
                mma_f16(o[jc], ap, bf);
            }
        }
    }

    float inv0 = 1.f / l0, inv1 = 1.f / l1;
    int t = t0 + wid*16 + g;
    size_t rowbase = (size_t)b*TOK;
    #pragma unroll
    for (int jc = 0; jc < 8; jc++) {
        int cc = h*HD + jc*8 + tg*2;
        *(__half2*)&g_netT[(rowbase + t  )*CH + cc] =
            __floats2half2_rn(o[jc][0]*inv0, o[jc][1]*inv0);
        *(__half2*)&g_netT[(rowbase + t+8)*CH + cc] =
            __floats2half2_rn(o[jc][2]*inv1, o[jc][3]*inv1);
    }
}

// ---------------------------------------------------------------------------
extern "C" void kernel_launch(void* const* d_in, const int* in_sizes, int n_in,
                              void* d_out, int out_size)
{
    const float* x     = (const float*)d_in[0];
    const float* gn_w  = (const float*)d_in[1];
    const float* gn_b  = (const float*)d_in[2];
    const float* qkv_w = (const float*)d_in[3];
    const float* qkv_b = (const float*)d_in[4];
    const float* out_w = (const float*)d_in[5];
    const float* out_b = (const float*)d_in[6];
    float* out = (float*)d_out;

    __half *nT, *wqkv, *wout, *netT;
    cudaGetSymbolAddress((void**)&nT,   g_nT);
    cudaGetSymbolAddress((void**)&wqkv, g_wqkv);
    cudaGetSymbolAddress((void**)&wout, g_wout);
    cudaGetSymbolAddress((void**)&netT, g_netT);

    cvt_w_kernel<<<1024, 256>>>(qkv_w, out_w);
    gn_kernel<<<BATCH*GROUPS, 256>>>(x, gn_w, gn_b);
    gemm_h<0><<<dim3(12, 8, BATCH), 256>>>(nT, wqkv, qkv_b, nullptr, nullptr);
    flash_kernel<<<dim3(16, NHEAD), 128>>>();
    gemm_h<1><<<dim3(8, 4, BATCH), 256>>>(wout, netT, out_b, x, out);
}

// round 4
// speedup vs baseline: 7.1318x; 1.0845x over previous
#include <cuda_runtime.h>
#include <cuda_fp16.h>
#include <cstddef>
#include <cstdint>

#define BATCH 8
#define CH    512
#define TOK   1024
#define HEADS 8
#define HD    64
#define NHEAD (BATCH*HEADS)   // 64
#define GROUPS 32
#define CPG   16

#define QSCALE 0.1803368801111204f   // 0.125 * log2(e)

// ---------------- scratch (__device__ globals; alloc-free rule) -------------
__device__ __align__(16) __half g_nT  [(size_t)BATCH*TOK*CH];    // [b][t][c]
__device__ __align__(16) __half g_wqkv[(size_t)3*CH*CH];         // [och][c]
__device__ __align__(16) __half g_wout[(size_t)CH*CH];           // [och][c]
__device__ __align__(16) __half g_q   [(size_t)NHEAD*TOK*HD];    // [head][t][c]  (x QSCALE)
__device__ __align__(16) __half g_k   [(size_t)NHEAD*TOK*HD];    // [head][s][c]
__device__ __align__(16) __half g_v   [(size_t)NHEAD*HD*TOK];    // [head][c][s]
__device__ __align__(16) __half g_netT[(size_t)BATCH*TOK*CH];    // [b][t][c]

// ---------------- helpers ---------------------------------------------------
__device__ __forceinline__ void mma_f16(float* c, const uint32_t* a, const uint32_t* b)
{
    asm volatile(
        "mma.sync.aligned.m16n8k16.row.col.f32.f16.f16.f32 "
        "{%0,%1,%2,%3},{%4,%5,%6,%7},{%8,%9},{%0,%1,%2,%3};"
        : "+f"(c[0]), "+f"(c[1]), "+f"(c[2]), "+f"(c[3])
        : "r"(a[0]), "r"(a[1]), "r"(a[2]), "r"(a[3]), "r"(b[0]), "r"(b[1]));
}

__device__ __forceinline__ uint32_t pack_h2(float lo, float hi)
{
    __half2 h = __floats2half2_rn(lo, hi);
    return *reinterpret_cast<uint32_t*>(&h);
}

__device__ __forceinline__ float ex2(float x)
{
    float y;
    asm("ex2.approx.ftz.f32 %0, %1;" : "=f"(y) : "f"(x));
    return y;
}

__device__ __forceinline__ void cp16(void* s, const void* g)
{
    uint32_t sa = (uint32_t)__cvta_generic_to_shared(s);
    asm volatile("cp.async.cg.shared.global [%0], [%1], 16;\n" :: "r"(sa), "l"(g));
}
#define CP_COMMIT() asm volatile("cp.async.commit_group;\n" ::: "memory")
#define CP_WAIT1()  asm volatile("cp.async.wait_group 1;\n" ::: "memory")
#define CP_WAIT0()  asm volatile("cp.async.wait_group 0;\n" ::: "memory")

// ---------------------------------------------------------------------------
// Kernel 0: convert weights fp32 -> fp16
// ---------------------------------------------------------------------------
__global__ void cvt_w_kernel(const float* __restrict__ qkvw,
                             const float* __restrict__ outw)
{
    int i = blockIdx.x * 256 + threadIdx.x;     // one float4 each
    const int N1 = 3*CH*CH/4;
    const int N2 = CH*CH/4;
    if (i < N1) {
        float4 v = *(const float4*)(qkvw + (size_t)i*4);
        __half* d = g_wqkv + (size_t)i*4;
        d[0]=__float2half_rn(v.x); d[1]=__float2half_rn(v.y);
        d[2]=__float2half_rn(v.z); d[3]=__float2half_rn(v.w);
    } else if (i < N1 + N2) {
        int j = i - N1;
        float4 v = *(const float4*)(outw + (size_t)j*4);
        __half* d = g_wout + (size_t)j*4;
        d[0]=__float2half_rn(v.x); d[1]=__float2half_rn(v.y);
        d[2]=__float2half_rn(v.z); d[3]=__float2half_rn(v.w);
    }
}

// ---------------------------------------------------------------------------
// Kernel 1: GroupNorm -> g_nT[b][t][c] (half), transposed via smem tiles.
// ---------------------------------------------------------------------------
__global__ void gn_kernel(const float* __restrict__ x,
                          const float* __restrict__ w,
                          const float* __restrict__ bb)
{
    int blk = blockIdx.x;
    int b = blk >> 5, gg = blk & 31;
    const float* src = x + ((size_t)b*CH + gg*CPG) * TOK;
    int tid = threadIdx.x;
    const int N = CPG * TOK;   // 16384

    float s = 0.f, ss = 0.f;
    for (int i = tid*4; i < N; i += 256*4) {
        float4 v = *(const float4*)(src + i);
        s  += v.x + v.y + v.z + v.w;
        ss += v.x*v.x + v.y*v.y + v.z*v.z + v.w*v.w;
    }
    for (int o = 16; o; o >>= 1) {
        s  += __shfl_down_sync(~0u, s,  o);
        ss += __shfl_down_sync(~0u, ss, o);
    }
    __shared__ float shs[8], shq[8];
    __shared__ float f_mu, f_rstd;
    if ((tid & 31) == 0) { shs[tid>>5] = s; shq[tid>>5] = ss; }
    __syncthreads();
    if (tid == 0) {
        float ts = 0.f, tq = 0.f;
        #pragma unroll
        for (int i = 0; i < 8; i++) { ts += shs[i]; tq += shq[i]; }
        float mu  = ts / N;
        f_mu = mu;
        f_rstd = rsqrtf(tq / N - mu*mu + 1e-5f);
    }
    __syncthreads();
    float mu = f_mu, rstd = f_rstd;

    __shared__ __align__(16) __half tile[16][68];
    int c  = tid >> 4;
    int tl = (tid & 15) * 4;
    float scw = w[gg*CPG + c] * rstd;
    float scb = bb[gg*CPG + c] - mu * scw;
    int tw  = tid >> 2;
    int c4  = (tid & 3) * 4;
    for (int t0 = 0; t0 < TOK; t0 += 64) {
        float4 v = *(const float4*)(src + (size_t)c*TOK + t0 + tl);
        __half2 h0 = __floats2half2_rn(v.x*scw+scb, v.y*scw+scb);
        __half2 h1 = __floats2half2_rn(v.z*scw+scb, v.w*scw+scb);
        *(__half2*)&tile[c][tl]   = h0;
        *(__half2*)&tile[c][tl+2] = h1;
        __syncthreads();
        __half* dst = g_nT + ((size_t)b*TOK + t0 + tw)*CH + gg*CPG + c4;
        *(__half2*)(dst)   = __halves2half2(tile[c4  ][tw], tile[c4+1][tw]);
        *(__half2*)(dst+2) = __halves2half2(tile[c4+2][tw], tile[c4+3][tw]);
        __syncthreads();
    }
}

// ---------------------------------------------------------------------------
// Kernel 2/4: half GEMM, C[m][n] = sum_k A[m][k] * B[n][k], K=512.
// 128x128 block tile, 8 warps, double-buffered smem via cp.async.
// ---------------------------------------------------------------------------
template<int MODE>
__global__ void __launch_bounds__(256)
gemm_h(const __half* __restrict__ Abase, const __half* __restrict__ Bbase,
       const float* __restrict__ bias, const float* __restrict__ res,
       float* __restrict__ Cout)
{
    __shared__ __align__(16) __half As[2][128][40];
    __shared__ __align__(16) __half Bs[2][128][40];

    int bz = blockIdx.z;
    const __half* A = Abase + (MODE == 0 ? (size_t)bz*TOK*CH : 0);
    const __half* B = Bbase + (MODE == 1 ? (size_t)bz*TOK*CH : 0);

    int m0 = blockIdx.y * 128, n0 = blockIdx.x * 128;
    int tid = threadIdx.x, wid = tid >> 5, lane = tid & 31;
    int g = lane >> 2, tg = lane & 3;
    int wm = wid & 3, wn = wid >> 2;

    int lr = tid >> 2;
    int lc = (tid & 3) * 8;

    // prefetch k-step 0
    cp16(&As[0][lr   ][lc], A + (size_t)(m0+lr   )*CH + lc);
    cp16(&As[0][lr+64][lc], A + (size_t)(m0+lr+64)*CH + lc);
    cp16(&Bs[0][lr   ][lc], B + (size_t)(n0+lr   )*CH + lc);
    cp16(&Bs[0][lr+64][lc], B + (size_t)(n0+lr+64)*CH + lc);
    CP_COMMIT();

    float acc[2][8][4] = {};

    for (int ks = 0; ks < 16; ks++) {
        int buf = ks & 1;
        if (ks + 1 < 16) {
            int k1 = (ks+1) * 32;
            cp16(&As[buf^1][lr   ][lc], A + (size_t)(m0+lr   )*CH + k1 + lc);
            cp16(&As[buf^1][lr+64][lc], A + (size_t)(m0+lr+64)*CH + k1 + lc);
            cp16(&Bs[buf^1][lr   ][lc], B + (size_t)(n0+lr   )*CH + k1 + lc);
            cp16(&Bs[buf^1][lr+64][lc], B + (size_t)(n0+lr+64)*CH + k1 + lc);
            CP_COMMIT();
            CP_WAIT1();
        } else {
            CP_WAIT0();
        }
        __syncthreads();
        #pragma unroll
        for (int kk = 0; kk < 2; kk++) {
            uint32_t af[2][4], bf[8][2];
            int kc = kk*16 + tg*2;
            #pragma unroll
            for (int i = 0; i < 2; i++) {
                int mr = wm*32 + i*16 + g;
                af[i][0] = *(const uint32_t*)&As[buf][mr  ][kc];
                af[i][1] = *(const uint32_t*)&As[buf][mr+8][kc];
                af[i][2] = *(const uint32_t*)&As[buf][mr  ][kc+8];
                af[i][3] = *(const uint32_t*)&As[buf][mr+8][kc+8];
            }
            #pragma unroll
            for (int j = 0; j < 8; j++) {
                int nr = wn*64 + j*8 + g;
                bf[j][0] = *(const uint32_t*)&Bs[buf][nr][kc];
                bf[j][1] = *(const uint32_t*)&Bs[buf][nr][kc+8];
            }
            #pragma unroll
            for (int i = 0; i < 2; i++)
                #pragma unroll
                for (int j = 0; j < 8; j++)
                    mma_f16(acc[i][j], af[i], bf[j]);
        }
        __syncthreads();
    }

    if (MODE == 0) {
        #pragma unroll
        for (int j = 0; j < 8; j++) {
            int n = n0 + wn*64 + j*8 + tg*2;      // och
            float bi0 = bias[n], bi1 = bias[n+1];
            int hh = n / 192, r = n % 192;
            #pragma unroll
            for (int i = 0; i < 2; i++) {
                int t = m0 + wm*32 + i*16 + g;
                float v00 = acc[i][j][0]+bi0, v01 = acc[i][j][1]+bi1;
                float v10 = acc[i][j][2]+bi0, v11 = acc[i][j][3]+bi1;
                size_t hb = (size_t)(bz*HEADS + hh);
                if (r < 64) {
                    v00*=QSCALE; v01*=QSCALE; v10*=QSCALE; v11*=QSCALE;
                    __half* q = g_q + (hb*TOK)*HD + r;
                    *(__half2*)(q + (size_t)t    *HD) = __floats2half2_rn(v00, v01);
                    *(__half2*)(q + (size_t)(t+8)*HD) = __floats2half2_rn(v10, v11);
                } else if (r < 128) {
                    __half* k = g_k + (hb*TOK)*HD + (r-64);
                    *(__half2*)(k + (size_t)t    *HD) = __floats2half2_rn(v00, v01);
                    *(__half2*)(k + (size_t)(t+8)*HD) = __floats2half2_rn(v10, v11);
                } else {
                    int cc = r - 128;
                    __half* v = g_v + (hb*HD + cc)*TOK;
                    v[t]         = __float2half_rn(v00);
                    v[TOK + t]   = __float2half_rn(v01);
                    v[t+8]       = __float2half_rn(v10);
                    v[TOK + t+8] = __float2half_rn(v11);
                }
            }
        }
    } else {
        #pragma unroll
        for (int j = 0; j < 8; j++) {
            int n = n0 + wn*64 + j*8 + tg*2;
            #pragma unroll
            for (int i = 0; i < 2; i++) {
                int m = m0 + wm*32 + i*16 + g;
                float ob0 = bias[m], ob1 = bias[m+8];
                size_t o0 = ((size_t)bz*CH + m)*TOK + n;
                size_t o1 = ((size_t)bz*CH + m+8)*TOK + n;
                float2 r0 = *(const float2*)(res + o0);
                float2 r1 = *(const float2*)(res + o1);
                float2 w0 = { acc[i][j][0]+ob0+r0.x, acc[i][j][1]+ob0+r0.y };
                float2 w1 = { acc[i][j][2]+ob1+r1.x, acc[i][j][3]+ob1+r1.y };
                *(float2*)(Cout + o0) = w0;
                *(float2*)(Cout + o1) = w1;
            }
        }
    }
}

// ---------------------------------------------------------------------------
// Kernel 3: flash attention, double-buffered K/V via cp.async, exp2 softmax.
// One block = (head, 64 q-rows). 128 threads, 4 warps x 16 q-rows.
// ---------------------------------------------------------------------------
__global__ void __launch_bounds__(128) flash_kernel()
{
    int head = blockIdx.y;
    int b = head >> 3, h = head & 7;
    int t0 = blockIdx.x * 64;
    const __half* Qg = g_q + ((size_t)head*TOK + t0)*HD;
    const __half* Kg = g_k + (size_t)head*TOK*HD;
    const __half* Vg = g_v + (size_t)head*HD*TOK;

    __shared__ __align__(16) __half Qs[64][72];
    __shared__ __align__(16) __half Ks[2][64][72];
    __shared__ __align__(16) __half Vs[2][64][72];

    int tid = threadIdx.x, wid = tid >> 5, lane = tid & 31;
    int g = lane >> 2, tg = lane & 3;

    #pragma unroll
    for (int p = 0; p < 4; p++) {
        int u = tid + p*128;
        int r = u >> 3, cg = (u & 7) * 8;
        *(uint4*)&Qs[r][cg] = *(const uint4*)(Qg + (size_t)r*HD + cg);
    }
    // prefetch s-tile 0
    #pragma unroll
    for (int p = 0; p < 4; p++) {
        int u = tid + p*128;
        int r = u >> 3, cg = (u & 7) * 8;
        cp16(&Ks[0][r][cg], Kg + (size_t)r*HD + cg);
        cp16(&Vs[0][r][cg], Vg + (size_t)r*TOK + cg);
    }
    CP_COMMIT();
    __syncthreads();

    uint32_t aq[4][4];
    #pragma unroll
    for (int kk = 0; kk < 4; kk++) {
        int mr = wid*16 + g, kc = kk*16 + tg*2;
        aq[kk][0] = *(const uint32_t*)&Qs[mr  ][kc];
        aq[kk][1] = *(const uint32_t*)&Qs[mr+8][kc];
        aq[kk][2] = *(const uint32_t*)&Qs[mr  ][kc+8];
        aq[kk][3] = *(const uint32_t*)&Qs[mr+8][kc+8];
    }

    float m0 = -1e30f, m1 = -1e30f, l0 = 0.f, l1 = 0.f;
    float o[8][4] = {};

    for (int it = 0; it < 16; it++) {
        int buf = it & 1;
        if (it + 1 < 16) {
            int s1 = (it+1)*64;
            #pragma unroll
            for (int p = 0; p < 4; p++) {
                int u = tid + p*128;
                int r = u >> 3, cg = (u & 7) * 8;
                cp16(&Ks[buf^1][r][cg], Kg + (size_t)(s1+r)*HD + cg);
                cp16(&Vs[buf^1][r][cg], Vg + (size_t)r*TOK + s1 + cg);
            }
            CP_COMMIT();
            CP_WAIT1();
        } else {
            CP_WAIT0();
        }
        __syncthreads();

        float sc[8][4] = {};
        #pragma unroll
        for (int kk = 0; kk < 4; kk++) {
            int kc = kk*16 + tg*2;
            #pragma unroll
            for (int j = 0; j < 8; j++) {
                uint32_t bf[2];
                bf[0] = *(const uint32_t*)&Ks[buf][j*8+g][kc];
                bf[1] = *(const uint32_t*)&Ks[buf][j*8+g][kc+8];
                mma_f16(sc[j], aq[kk], bf);
            }
        }

        // online softmax in log2 domain (q was pre-scaled by 0.125*log2e)
        float mx0 = -1e30f, mx1 = -1e30f;
        #pragma unroll
        for (int j = 0; j < 8; j++) {
            mx0 = fmaxf(mx0, fmaxf(sc[j][0], sc[j][1]));
            mx1 = fmaxf(mx1, fmaxf(sc[j][2], sc[j][3]));
        }
        mx0 = fmaxf(mx0, __shfl_xor_sync(~0u, mx0, 1));
        mx0 = fmaxf(mx0, __shfl_xor_sync(~0u, mx0, 2));
        mx1 = fmaxf(mx1, __shfl_xor_sync(~0u, mx1, 1));
        mx1 = fmaxf(mx1, __shfl_xor_sync(~0u, mx1, 2));
        float nm0 = fmaxf(m0, mx0), nm1 = fmaxf(m1, mx1);
        float f0 = ex2(m0 - nm0), f1 = ex2(m1 - nm1);
        m0 = nm0; m1 = nm1;
        float s0s = 0.f, s1s = 0.f;
        #pragma unroll
        for (int j = 0; j < 8; j++) {
            sc[j][0] = ex2(sc[j][0] - nm0);
            sc[j][1] = ex2(sc[j][1] - nm0);
            sc[j][2] = ex2(sc[j][2] - nm1);
            sc[j][3] = ex2(sc[j][3] - nm1);
            s0s += sc[j][0] + sc[j][1];
            s1s += sc[j][2] + sc[j][3];
        }
        s0s += __shfl_xor_sync(~0u, s0s, 1);
        s0s += __shfl_xor_sync(~0u, s0s, 2);
        s1s += __shfl_xor_sync(~0u, s1s, 1);
        s1s += __shfl_xor_sync(~0u, s1s, 2);
        l0 = l0*f0 + s0s;
        l1 = l1*f1 + s1s;
        #pragma unroll
        for (int j = 0; j < 8; j++) {
            o[j][0] *= f0; o[j][1] *= f0; o[j][2] *= f1; o[j][3] *= f1;
        }

        // PV: acc[t][c] += P[t][s] * V[s][c]
        #pragma unroll
        for (int i = 0; i < 4; i++) {
            uint32_t ap[4];
            ap[0] = pack_h2(sc[2*i  ][0], sc[2*i  ][1]);
            ap[1] = pack_h2(sc[2*i  ][2], sc[2*i  ][3]);
            ap[2] = pack_h2(sc[2*i+1][0], sc[2*i+1][1]);
            ap[3] = pack_h2(sc[2*i+1][2], sc[2*i+1][3]);
            int kc = i*16 + tg*2;
            #pragma unroll
            for (int jc = 0; jc < 8; jc++) {
                uint32_t bf[2];
                bf[0] = *(const uint32_t*)&Vs[buf][jc*8+g][kc];
                bf[1] = *(const uint32_t*)&Vs[buf][jc*8+g][kc+8];
                mma_f16(o[jc], ap, bf);
            }
        }
        __syncthreads();
    }

    float inv0 = 1.f / l0, inv1 = 1.f / l1;
    int t = t0 + wid*16 + g;
    size_t rowbase = (size_t)b*TOK;
    #pragma unroll
    for (int jc = 0; jc < 8; jc++) {
        int cc = h*HD + jc*8 + tg*2;
        *(__half2*)&g_netT[(rowbase + t  )*CH + cc] =
            __floats2half2_rn(o[jc][0]*inv0, o[jc][1]*inv0);
        *(__half2*)&g_netT[(rowbase + t+8)*CH + cc] =
            __floats2half2_rn(o[jc][2]*inv1, o[jc][3]*inv1);
    }
}

// ---------------------------------------------------------------------------
extern "C" void kernel_launch(void* const* d_in, const int* in_sizes, int n_in,
                              void* d_out, int out_size)
{
    const float* x     = (const float*)d_in[0];
    const float* gn_w  = (const float*)d_in[1];
    const float* gn_b  = (const float*)d_in[2];
    const float* qkv_w = (const float*)d_in[3];
    const float* qkv_b = (const float*)d_in[4];
    const float* out_w = (const float*)d_in[5];
    const float* out_b = (const float*)d_in[6];
    float* out = (float*)d_out;

    __half *nT, *wqkv, *wout, *netT;
    cudaGetSymbolAddress((void**)&nT,   g_nT);
    cudaGetSymbolAddress((void**)&wqkv, g_wqkv);
    cudaGetSymbolAddress((void**)&wout, g_wout);
    cudaGetSymbolAddress((void**)&netT, g_netT);

    cvt_w_kernel<<<1024, 256>>>(qkv_w, out_w);
    gn_kernel<<<BATCH*GROUPS, 256>>>(x, gn_w, gn_b);
    gemm_h<0><<<dim3(12, 8, BATCH), 256>>>(nT, wqkv, qkv_b, nullptr, nullptr);
    flash_kernel<<<dim3(16, NHEAD), 128>>>();
    gemm_h<1><<<dim3(8, 4, BATCH), 256>>>(wout, netT, out_b, x, out);
}